// round 10
// baseline (speedup 1.0000x reference)
#include <cuda_runtime.h>
#include <cuda_bf16.h>
#include <cstdint>

// ---------------------------------------------------------------------------
// Fused ConvTranspose3d(3->16,k3,s2,p1) * 0.5 -> AvgPool(2) -> +bias  reduces
// to a dense stride-1 VALID conv with a 2x2x2 kernel.
// x: (4,3,128,128,128) fp32, out: (4,16,127,127,127) fp32
//
// Winograd F(2,2) along w: per (oc-pair, kh):
//   M1 += x1*(w0+w1); M2 += (x0-x1)*w0; M3 += (x2-x1)*w1
//   y[w]   = M1+M2 ;  y[w+1] = M1+M3        (3 FFMA2 instead of 4)
// Weight combos precomputed into constant memory; bias folded into M1 init.
// ---------------------------------------------------------------------------

#define IC 3
#define OC 16
#define DIN 128
#define DOUT 127

#define XNS 6291456   // 3*128^3
#define XCS 2097152   // 128^3
#define XZS 16384     // 128^2
#define OCS 2048383   // 127^3
#define ONS 32774128  // 16*127^3
#define OZS 16129     // 127^2
#define OYS 127

typedef unsigned long long ull;

// Winograd weights, oc-(even,odd)-paired as f32x2:
// ull index = (pair*6 + ickd)*6 + slot,
// slot: 0=ws(kh0) 1=ws(kh1) 2=w0(kh0) 3=w0(kh1) 4=w1(kh0) 5=w1(kh1)
//  ws = w(kw0)+w(kw1), w0 = w(kw=0), w1 = w(kw=1)
__device__ __align__(16) float g_w[8 * 6 * 6 * 2];
__device__ __align__(16) float g_b[16];

__constant__ __align__(16) ull c_w[8 * 6 * 6];
__constant__ __align__(16) ull c_b[8];

__device__ float fold_tap(const float* cw, int ic, int oc,
                          int kd, int kh, int kw) {
    // fold index0 -> taps {1,2}; index1 -> tap {0}; conv_weight (3,16,3,3,3)
    int plo = kd ? 0 : 1, phi = kd ? 0 : 2;
    int qlo = kh ? 0 : 1, qhi = kh ? 0 : 2;
    int rlo = kw ? 0 : 1, rhi = kw ? 0 : 2;
    float s = 0.f;
    for (int p = plo; p <= phi; ++p)
        for (int q = qlo; q <= qhi; ++q)
            for (int r = rlo; r <= rhi; ++r)
                s += cw[ic * 432 + oc * 27 + p * 9 + q * 3 + r];
    return s * 0.0625f;
}

__global__ void fold_weights_kernel(const float* __restrict__ cw,
                                    const float* __restrict__ cb,
                                    const float* __restrict__ eb) {
    int i = blockIdx.x * blockDim.x + threadIdx.x;
    if (i < 576) {
        int eo = i & 1, t = i >> 1;
        int slot = t % 6;  t /= 6;
        int ickd = t % 6;
        int pair = t / 6;
        int oc = 2 * pair + eo;
        int ic = ickd >> 1, kd = ickd & 1;
        int kh = slot & 1;
        float v;
        if (slot < 2)      v = fold_tap(cw, ic, oc, kd, kh, 0) +
                               fold_tap(cw, ic, oc, kd, kh, 1);
        else if (slot < 4) v = fold_tap(cw, ic, oc, kd, kh, 0);
        else               v = fold_tap(cw, ic, oc, kd, kh, 1);
        g_w[((pair * 6 + ickd) * 6 + slot) * 2 + eo] = v;
    } else if (i < 592) {
        int oc = i - 576;
        g_b[oc] = cb[oc] * 0.5f + eb[oc];
    }
}

// ---- packed fp32x2 helpers (Blackwell FFMA2/FADD2; ptxas won't emit from C++)
__device__ __forceinline__ void ffma2(ull& d, ull a, ull b) {
    asm("fma.rn.f32x2 %0, %1, %2, %0;" : "+l"(d) : "l"(a), "l"(b));
}
__device__ __forceinline__ ull fadd2(ull a, ull b) {
    ull r; asm("add.rn.f32x2 %0, %1, %2;" : "=l"(r) : "l"(a), "l"(b));
    return r;
}
__device__ __forceinline__ ull rep2(float v) {
    ull r; unsigned u = __float_as_uint(v);
    asm("mov.b64 %0, {%1, %1};" : "=l"(r) : "r"(u));
    return r;
}
__device__ __forceinline__ float lo2(ull a) { return __uint_as_float((unsigned)a); }
__device__ __forceinline__ float hi2(ull a) { return __uint_as_float((unsigned)(a >> 32)); }

#define ROWW 132   // pad: seg1/lane31 reads rp[w0+2]=rp[128] (masked output)

// Block: 128 threads = 32 lanes x 2 w-segs x 2 oc-octets.
// Thread: outputs (w0, w0+1) x 8 oc x 2 h-rows per iter; w0 = 64*seg + 2*lane.
// Grid: (16 h-tiles, 127 d, 4 n)
__global__ void __launch_bounds__(128, 6)
conv2x2x2_kernel(const float* __restrict__ x, float* __restrict__ out) {
    __shared__ __align__(16) float tile[IC][2][9][ROWW];   // 28512 B

    const int tid  = threadIdx.x;
    const int lane = tid & 31;
    const int warp = tid >> 5;
    const int og   = warp & 1;      // oc octet
    const int seg  = warp >> 1;     // w segment
    const int ht = blockIdx.x;
    const int d  = blockIdx.y;
    const int n  = blockIdx.z;
    const int h0 = ht * 8;

    // ---- load x tile: 3 ic x 2 d-planes x 9 h rows x 128 w (rows padded)
    {
        const float* xb = x + (size_t)n * XNS + (size_t)d * XZS;
        for (int i = tid; i < 54 * 32; i += 128) {
            int row = i >> 5;
            int col = (i & 31) << 2;
            int ic  = row / 18;
            int rem = row - ic * 18;
            int dz  = rem / 9;
            int hy  = rem - dz * 9;
            int gy  = h0 + hy;
            if (gy > 127) gy = 127;   // clamp (last tile); rows unused by stores
            const float4 v = *(const float4*)(xb + (size_t)ic * XCS +
                                              (size_t)dz * XZS + gy * DIN + col);
            *(float4*)&tile[ic][dz][hy][col] = v;
        }
    }

    __syncthreads();

    const int w0 = seg * 64 + 2 * lane;
    const bool wlast = (seg == 1) && (lane == 31);  // w0 = 126 (w=127 invalid)
    float* obase = out + (size_t)n * ONS + (size_t)(8 * og) * OCS +
                   (size_t)d * OZS + w0;

#pragma unroll 1
    for (int hl = 0; hl < 8; hl += 2) {
        const int h = h0 + hl;
        if (h >= DOUT) break;      // uniform across block

        // Winograd accumulators: M[row][m][pair], m: 0=M1 1=M2 2=M3
        ull M[2][3][4];
#pragma unroll
        for (int p = 0; p < 4; ++p) {
            const ull fb = c_b[4 * og + p];       // LDC (uniform)
            M[0][0][p] = fb; M[0][1][p] = 0; M[0][2][p] = 0;
            M[1][0][p] = fb; M[1][1][p] = 0; M[1][2][p] = 0;
        }

#pragma unroll 1
        for (int ickd = 0; ickd < 6; ++ickd) {
            const int ic = ickd >> 1, kd = ickd & 1;

            // weights via constant port: 3 x LDC.128 per pair
            ulonglong2 WS[4], W0[4], W1[4];   // each: (.x = kh0, .y = kh1)
#pragma unroll
            for (int p = 0; p < 4; ++p) {
                const ull* cp = &c_w[((4 * og + p) * 6 + ickd) * 6];
                WS[p] = *(const ulonglong2*)(cp);
                W0[p] = *(const ulonglong2*)(cp + 2);
                W1[p] = *(const ulonglong2*)(cp + 4);
            }

#pragma unroll
            for (int r = 0; r < 3; ++r) {
                const float* rp = &tile[ic][kd][hl + r][0];
                const float2 x01 = *(const float2*)(rp + w0);   // dense LDS.64
                const float  xx2 = rp[w0 + 2];   // LDS.32, 2-way conflict only
                const float dx0 = x01.x - x01.y;   // x0 - x1
                const float dx2 = xx2   - x01.y;   // x2 - x1
                const ull X1  = rep2(x01.y);
                const ull XD0 = rep2(dx0);
                const ull XD2 = rep2(dx2);

                if (r < 2) {     // kh=0 contribution to row r
#pragma unroll
                    for (int p = 0; p < 4; ++p) {
                        ffma2(M[r][0][p], X1,  WS[p].x);
                        ffma2(M[r][1][p], XD0, W0[p].x);
                        ffma2(M[r][2][p], XD2, W1[p].x);
                    }
                }
                if (r >= 1) {    // kh=1 contribution to row r-1
#pragma unroll
                    for (int p = 0; p < 4; ++p) {
                        ffma2(M[r - 1][0][p], X1,  WS[p].y);
                        ffma2(M[r - 1][1][p], XD0, W0[p].y);
                        ffma2(M[r - 1][2][p], XD2, W1[p].y);
                    }
                }
            }
        }

        // ---- epilogue + stores: y0 = M1+M2 (@w0), y1 = M1+M3 (@w0+1)
        // parity of row base for oc=8og+j: (j + d + h') & 1
#pragma unroll
        for (int rw = 0; rw < 2; ++rw) {
            const int hh = h + rw;
            if (rw && hh >= DOUT) break;
            const int par = (d + hh) & 1;
#pragma unroll
            for (int p = 0; p < 4; ++p) {
                const ull y0 = fadd2(M[rw][0][p], M[rw][1][p]);  // @ w0
                const ull y1 = fadd2(M[rw][0][p], M[rw][2][p]);  // @ w0+1
                // j = 2p (even oc -> lo halves)
                {
                    float* o = obase + (size_t)(2 * p) * OCS + (size_t)hh * OYS;
                    const float v0 = lo2(y0), v1 = lo2(y1);
                    if (par == 0) {                // (j even) -> base parity = par
                        if (!wlast) *(float2*)o = make_float2(v0, v1);
                        else        o[0] = v0;
                    } else {
                        o[0] = v0;
                        if (!wlast) o[1] = v1;
                    }
                }
                // j = 2p+1 (odd oc -> hi halves), parity flipped
                {
                    float* o = obase + (size_t)(2 * p + 1) * OCS + (size_t)hh * OYS;
                    const float v0 = hi2(y0), v1 = hi2(y1);
                    if (par != 0) {
                        if (!wlast) *(float2*)o = make_float2(v0, v1);
                        else        o[0] = v0;
                    } else {
                        o[0] = v0;
                        if (!wlast) o[1] = v1;
                    }
                }
            }
        }
    }
}

extern "C" void kernel_launch(void* const* d_in, const int* in_sizes, int n_in,
                              void* d_out, int out_size) {
    const float* x  = (const float*)d_in[0];
    const float* cw = (const float*)d_in[1];
    const float* cb = (const float*)d_in[2];
    const float* eb = (const float*)d_in[3];
    float* out = (float*)d_out;

    fold_weights_kernel<<<1, 640>>>(cw, cb, eb);

    // Publish folded weights to constant memory (D2D memcpy, capturable).
    void *gw = nullptr, *gb = nullptr;
    cudaGetSymbolAddress(&gw, g_w);
    cudaGetSymbolAddress(&gb, g_b);
    cudaMemcpyToSymbolAsync(c_w, gw, sizeof(c_w), 0, cudaMemcpyDeviceToDevice, 0);
    cudaMemcpyToSymbolAsync(c_b, gb, sizeof(c_b), 0, cudaMemcpyDeviceToDevice, 0);

    dim3 grid(16, DOUT, 4);   // h-tiles, d, n
    conv2x2x2_kernel<<<grid, 128>>>(x, out);
}

// round 11
// speedup vs baseline: 1.0304x; 1.0304x over previous
#include <cuda_runtime.h>
#include <cuda_bf16.h>
#include <cstdint>

// ---------------------------------------------------------------------------
// Fused ConvTranspose3d(3->16,k3,s2,p1) * 0.5 -> AvgPool(2) -> +bias  reduces
// to a dense stride-1 VALID conv with a 2x2x2 kernel.
// x: (4,3,128,128,128) fp32, out: (4,16,127,127,127) fp32
//
// Winograd F(2,2) along w: per (oc-pair, kh):
//   M1 += x1*(w0+w1); M2 += (x0-x1)*w0; M3 += (x2-x1)*w1
//   y[w]   = M1+M2 ;  y[w+1] = M1+M3        (3 FFMA2 instead of 4)
// Weight combos precomputed into constant memory; bias folded into M1 init.
// Mainloop FULLY UNROLLED so ptxas can batch LDS/LDC and hide latency.
// ---------------------------------------------------------------------------

#define IC 3
#define OC 16
#define DIN 128
#define DOUT 127

#define XNS 6291456   // 3*128^3
#define XCS 2097152   // 128^3
#define XZS 16384     // 128^2
#define OCS 2048383   // 127^3
#define ONS 32774128  // 16*127^3
#define OZS 16129     // 127^2
#define OYS 127

typedef unsigned long long ull;

// Winograd weights, oc-(even,odd)-paired as f32x2:
// ull index = (pair*6 + ickd)*6 + slot,
// slot: 0=ws(kh0) 1=ws(kh1) 2=w0(kh0) 3=w0(kh1) 4=w1(kh0) 5=w1(kh1)
//  ws = w(kw0)+w(kw1), w0 = w(kw=0), w1 = w(kw=1)
__device__ __align__(16) float g_w[8 * 6 * 6 * 2];
__device__ __align__(16) float g_b[16];

__constant__ __align__(16) ull c_w[8 * 6 * 6];
__constant__ __align__(16) ull c_b[8];

__device__ float fold_tap(const float* cw, int ic, int oc,
                          int kd, int kh, int kw) {
    // fold index0 -> taps {1,2}; index1 -> tap {0}; conv_weight (3,16,3,3,3)
    int plo = kd ? 0 : 1, phi = kd ? 0 : 2;
    int qlo = kh ? 0 : 1, qhi = kh ? 0 : 2;
    int rlo = kw ? 0 : 1, rhi = kw ? 0 : 2;
    float s = 0.f;
    for (int p = plo; p <= phi; ++p)
        for (int q = qlo; q <= qhi; ++q)
            for (int r = rlo; r <= rhi; ++r)
                s += cw[ic * 432 + oc * 27 + p * 9 + q * 3 + r];
    return s * 0.0625f;
}

__global__ void fold_weights_kernel(const float* __restrict__ cw,
                                    const float* __restrict__ cb,
                                    const float* __restrict__ eb) {
    int i = blockIdx.x * blockDim.x + threadIdx.x;
    if (i < 576) {
        int eo = i & 1, t = i >> 1;
        int slot = t % 6;  t /= 6;
        int ickd = t % 6;
        int pair = t / 6;
        int oc = 2 * pair + eo;
        int ic = ickd >> 1, kd = ickd & 1;
        int kh = slot & 1;
        float v;
        if (slot < 2)      v = fold_tap(cw, ic, oc, kd, kh, 0) +
                               fold_tap(cw, ic, oc, kd, kh, 1);
        else if (slot < 4) v = fold_tap(cw, ic, oc, kd, kh, 0);
        else               v = fold_tap(cw, ic, oc, kd, kh, 1);
        g_w[((pair * 6 + ickd) * 6 + slot) * 2 + eo] = v;
    } else if (i < 592) {
        int oc = i - 576;
        g_b[oc] = cb[oc] * 0.5f + eb[oc];
    }
}

// ---- packed fp32x2 helpers (Blackwell FFMA2/FADD2; ptxas won't emit from C++)
__device__ __forceinline__ void ffma2(ull& d, ull a, ull b) {
    asm("fma.rn.f32x2 %0, %1, %2, %0;" : "+l"(d) : "l"(a), "l"(b));
}
__device__ __forceinline__ ull fadd2(ull a, ull b) {
    ull r; asm("add.rn.f32x2 %0, %1, %2;" : "=l"(r) : "l"(a), "l"(b));
    return r;
}
__device__ __forceinline__ ull rep2(float v) {
    ull r; unsigned u = __float_as_uint(v);
    asm("mov.b64 %0, {%1, %1};" : "=l"(r) : "r"(u));
    return r;
}
__device__ __forceinline__ float lo2(ull a) { return __uint_as_float((unsigned)a); }
__device__ __forceinline__ float hi2(ull a) { return __uint_as_float((unsigned)(a >> 32)); }

#define ROWW 132   // pad: seg1/lane31 reads rp[w0+2]=rp[128] (masked output)

// Block: 128 threads = 32 lanes x 2 w-segs x 2 oc-octets.
// Thread: outputs (w0, w0+1) x 8 oc x 2 h-rows per iter; w0 = 64*seg + 2*lane.
// Grid: (16 h-tiles, 127 d, 4 n)
__global__ void __launch_bounds__(128, 6)
conv2x2x2_kernel(const float* __restrict__ x, float* __restrict__ out) {
    __shared__ __align__(16) float tile[IC][2][9][ROWW];   // 28512 B

    const int tid  = threadIdx.x;
    const int lane = tid & 31;
    const int warp = tid >> 5;
    const int og   = warp & 1;      // oc octet
    const int seg  = warp >> 1;     // w segment
    const int ht = blockIdx.x;
    const int d  = blockIdx.y;
    const int n  = blockIdx.z;
    const int h0 = ht * 8;

    // ---- load x tile: 3 ic x 2 d-planes x 9 h rows x 128 w (rows padded)
    {
        const float* xb = x + (size_t)n * XNS + (size_t)d * XZS;
        for (int i = tid; i < 54 * 32; i += 128) {
            int row = i >> 5;
            int col = (i & 31) << 2;
            int ic  = row / 18;
            int rem = row - ic * 18;
            int dz  = rem / 9;
            int hy  = rem - dz * 9;
            int gy  = h0 + hy;
            if (gy > 127) gy = 127;   // clamp (last tile); rows unused by stores
            const float4 v = *(const float4*)(xb + (size_t)ic * XCS +
                                              (size_t)dz * XZS + gy * DIN + col);
            *(float4*)&tile[ic][dz][hy][col] = v;
        }
    }

    __syncthreads();

    const int w0 = seg * 64 + 2 * lane;
    const bool wlast = (seg == 1) && (lane == 31);  // w0 = 126 (w=127 invalid)
    float* obase = out + (size_t)n * ONS + (size_t)(8 * og) * OCS +
                   (size_t)d * OZS + w0;

#pragma unroll 1
    for (int hl = 0; hl < 8; hl += 2) {
        const int h = h0 + hl;
        if (h >= DOUT) break;      // uniform across block

        // Winograd accumulators: M[row][m][pair], m: 0=M1 1=M2 2=M3
        ull M[2][3][4];
#pragma unroll
        for (int p = 0; p < 4; ++p) {
            const ull fb = c_b[4 * og + p];       // LDC (uniform)
            M[0][0][p] = fb; M[0][1][p] = 0; M[0][2][p] = 0;
            M[1][0][p] = fb; M[1][1][p] = 0; M[1][2][p] = 0;
        }

#pragma unroll
        for (int ickd = 0; ickd < 6; ++ickd) {
            const int ic = ickd >> 1, kd = ickd & 1;

            // weights via constant port: 3 x LDC.128 per pair
            ulonglong2 WS[4], W0[4], W1[4];   // each: (.x = kh0, .y = kh1)
#pragma unroll
            for (int p = 0; p < 4; ++p) {
                const ull* cp = &c_w[((4 * og + p) * 6 + ickd) * 6];
                WS[p] = *(const ulonglong2*)(cp);
                W0[p] = *(const ulonglong2*)(cp + 2);
                W1[p] = *(const ulonglong2*)(cp + 4);
            }

#pragma unroll
            for (int r = 0; r < 3; ++r) {
                const float* rp = &tile[ic][kd][hl + r][0];
                const float2 x01 = *(const float2*)(rp + w0);   // dense LDS.64
                const float  xx2 = rp[w0 + 2];   // LDS.32, 2-way conflict only
                const float dx0 = x01.x - x01.y;   // x0 - x1
                const float dx2 = xx2   - x01.y;   // x2 - x1
                const ull X1  = rep2(x01.y);
                const ull XD0 = rep2(dx0);
                const ull XD2 = rep2(dx2);

                if (r < 2) {     // kh=0 contribution to row r
#pragma unroll
                    for (int p = 0; p < 4; ++p) {
                        ffma2(M[r][0][p], X1,  WS[p].x);
                        ffma2(M[r][1][p], XD0, W0[p].x);
                        ffma2(M[r][2][p], XD2, W1[p].x);
                    }
                }
                if (r >= 1) {    // kh=1 contribution to row r-1
#pragma unroll
                    for (int p = 0; p < 4; ++p) {
                        ffma2(M[r - 1][0][p], X1,  WS[p].y);
                        ffma2(M[r - 1][1][p], XD0, W0[p].y);
                        ffma2(M[r - 1][2][p], XD2, W1[p].y);
                    }
                }
            }
        }

        // ---- epilogue + stores: y0 = M1+M2 (@w0), y1 = M1+M3 (@w0+1)
        // parity of row base for oc=8og+j: (j + d + h') & 1
#pragma unroll
        for (int rw = 0; rw < 2; ++rw) {
            const int hh = h + rw;
            if (rw && hh >= DOUT) break;
            const int par = (d + hh) & 1;
#pragma unroll
            for (int p = 0; p < 4; ++p) {
                const ull y0 = fadd2(M[rw][0][p], M[rw][1][p]);  // @ w0
                const ull y1 = fadd2(M[rw][0][p], M[rw][2][p]);  // @ w0+1
                // j = 2p (even oc -> lo halves)
                {
                    float* o = obase + (size_t)(2 * p) * OCS + (size_t)hh * OYS;
                    const float v0 = lo2(y0), v1 = lo2(y1);
                    if (par == 0) {                // (j even) -> base parity = par
                        if (!wlast) *(float2*)o = make_float2(v0, v1);
                        else        o[0] = v0;
                    } else {
                        o[0] = v0;
                        if (!wlast) o[1] = v1;
                    }
                }
                // j = 2p+1 (odd oc -> hi halves), parity flipped
                {
                    float* o = obase + (size_t)(2 * p + 1) * OCS + (size_t)hh * OYS;
                    const float v0 = hi2(y0), v1 = hi2(y1);
                    if (par != 0) {
                        if (!wlast) *(float2*)o = make_float2(v0, v1);
                        else        o[0] = v0;
                    } else {
                        o[0] = v0;
                        if (!wlast) o[1] = v1;
                    }
                }
            }
        }
    }
}

extern "C" void kernel_launch(void* const* d_in, const int* in_sizes, int n_in,
                              void* d_out, int out_size) {
    const float* x  = (const float*)d_in[0];
    const float* cw = (const float*)d_in[1];
    const float* cb = (const float*)d_in[2];
    const float* eb = (const float*)d_in[3];
    float* out = (float*)d_out;

    fold_weights_kernel<<<1, 640>>>(cw, cb, eb);

    // Publish folded weights to constant memory (D2D memcpy, capturable).
    void *gw = nullptr, *gb = nullptr;
    cudaGetSymbolAddress(&gw, g_w);
    cudaGetSymbolAddress(&gb, g_b);
    cudaMemcpyToSymbolAsync(c_w, gw, sizeof(c_w), 0, cudaMemcpyDeviceToDevice, 0);
    cudaMemcpyToSymbolAsync(c_b, gb, sizeof(c_b), 0, cudaMemcpyDeviceToDevice, 0);

    dim3 grid(16, DOUT, 4);   // h-tiles, d, n
    conv2x2x2_kernel<<<grid, 128>>>(x, out);
}